// round 14
// baseline (speedup 1.0000x reference)
#include <cuda_runtime.h>
#include <cuda_bf16.h>
#include <cstdint>
#include <math.h>

#define B_  8192
#define H_  1024
#define HH_ 512
#define M_  16
#define BM  128
#define BN  128
#define NTH 256
#define FBM 32
#define KSPLIT 4
#define MARGIN_THRESH 0.03f

typedef __nv_bfloat16 bf16;

// ---------------- scratch (device globals, no allocation) ----------------
__device__ bf16  g_qhi[B_ * H_];
__device__ bf16  g_qlo[B_ * H_];          // filled only for flagged rows
__device__ bf16  g_w1hi[HH_ * H_];
__device__ bf16  g_w1lo[HH_ * H_];
__device__ bf16  g_ew1b[M_ * HH_ * H_];
__device__ bf16  g_ew2b[M_ * H_ * HH_];
__device__ float g_X1[B_ * HH_];          // PRE-relu gating hidden
__device__ bf16  g_Hb[B_ * HH_];
__device__ bf16  g_Ob16[B_ * H_];
__device__ int   g_rows[M_ * B_];
__device__ int   g_cnt[M_];
__device__ int   g_flag[B_];
__device__ int   g_nflag;

// ---------------- PTX helpers ----------------
__device__ __forceinline__ uint32_t smem_u32(const void* p) {
    uint32_t a;
    asm("{ .reg .u64 t; cvta.to.shared.u64 t, %1; cvt.u32.u64 %0, t; }" : "=r"(a) : "l"(p));
    return a;
}
__device__ __forceinline__ void cp16(uint32_t dst, const void* src) {
    asm volatile("cp.async.cg.shared.global [%0], [%1], 16;" :: "r"(dst), "l"(src));
}
__device__ __forceinline__ void cp_commit() { asm volatile("cp.async.commit_group;" ::: "memory"); }
template <int N> __device__ __forceinline__ void cp_wait() {
    asm volatile("cp.async.wait_group %0;" :: "n"(N) : "memory");
}
__device__ __forceinline__ void ldmx4(uint32_t* r, uint32_t addr) {
    asm volatile("ldmatrix.sync.aligned.m8n8.x4.shared.b16 {%0,%1,%2,%3}, [%4];"
                 : "=r"(r[0]), "=r"(r[1]), "=r"(r[2]), "=r"(r[3]) : "r"(addr));
}
__device__ __forceinline__ void mma16816(float* d, const uint32_t* a, const uint32_t* b) {
    asm volatile(
        "mma.sync.aligned.m16n8k16.row.col.f32.bf16.bf16.f32 "
        "{%0,%1,%2,%3}, {%4,%5,%6,%7}, {%8,%9}, {%0,%1,%2,%3};"
        : "+f"(d[0]), "+f"(d[1]), "+f"(d[2]), "+f"(d[3])
        : "r"(a[0]), "r"(a[1]), "r"(a[2]), "r"(a[3]), "r"(b[0]), "r"(b[1]));
}

// ---------------- conversion helpers ----------------
__device__ __forceinline__ void cvt16v(const float* __restrict__ x, bf16* __restrict__ y) {
    float4 v[4];
#pragma unroll
    for (int c = 0; c < 4; c++) v[c] = *(const float4*)(x + c * 4);
    const float* vv = (const float*)v;
    __nv_bfloat162 p[8];
#pragma unroll
    for (int j = 0; j < 8; j++)
        p[j] = __nv_bfloat162(__float2bfloat16_rn(vv[2*j]), __float2bfloat16_rn(vv[2*j+1]));
    *(uint4*)y       = ((uint4*)p)[0];
    *(uint4*)(y + 8) = ((uint4*)p)[1];
}
__device__ __forceinline__ void split16v(const float* __restrict__ x,
                                         bf16* __restrict__ hi, bf16* __restrict__ lo) {
    float4 v[4];
#pragma unroll
    for (int c = 0; c < 4; c++) v[c] = *(const float4*)(x + c * 4);
    const float* vv = (const float*)v;
    __nv_bfloat162 hp[8], lp[8];
#pragma unroll
    for (int j = 0; j < 8; j++) {
        bf16 h0 = __float2bfloat16_rn(vv[2*j]);
        bf16 h1 = __float2bfloat16_rn(vv[2*j+1]);
        hp[j] = __nv_bfloat162(h0, h1);
        lp[j] = __nv_bfloat162(__float2bfloat16_rn(vv[2*j]   - __bfloat162float(h0)),
                               __float2bfloat16_rn(vv[2*j+1] - __bfloat162float(h1)));
    }
    *(uint4*)hi       = ((uint4*)hp)[0];
    *(uint4*)(hi + 8) = ((uint4*)hp)[1];
    *(uint4*)lo       = ((uint4*)lp)[0];
    *(uint4*)(lo + 8) = ((uint4*)lp)[1];
}

__global__ void bigcvt_k(const float* __restrict__ q, const float* __restrict__ c1w,
                         const float* __restrict__ ew1, const float* __restrict__ ew2) {
    if (blockIdx.x == 0) {
        if (threadIdx.x < M_) g_cnt[threadIdx.x] = 0;
        if (threadIdx.x == M_) g_nflag = 0;
    }
    const long N1 = (long)B_ * H_;
    const long N2 = (long)HH_ * H_;
    const long N3 = (long)M_ * HH_ * H_;
    const long N4 = (long)M_ * H_ * HH_;
    long i = ((long)blockIdx.x * blockDim.x + threadIdx.x) * 16;
    if (i < N1)                     cvt16v(q + i, g_qhi + i);
    else if (i < N1 + N2)           split16v(c1w + (i - N1), g_w1hi + (i - N1), g_w1lo + (i - N1));
    else if (i < N1 + N2 + N3)      cvt16v(ew1 + (i - N1 - N2), g_ew1b + (i - N1 - N2));
    else if (i < N1 + N2 + N3 + N4) cvt16v(ew2 + (i - N1 - N2 - N3), g_ew2b + (i - N1 - N2 - N3));
}

// ---------------- main HMMA GEMM (proven engine, row-tile loop) ----------
// 256 threads, 128x128 tile, 8 warps of 64x32, 3-stage cp.async pipeline.
// GROUPED: 0 = plain rows (grid sized exactly),
//          1 = per-expert (g_rows/g_cnt, blockIdx.z) with INTERNAL row-tile
//              loop: rt = blockIdx.x, blockIdx.x + gridDim.x, ...
template <int GROUPED, int RELU, typename OutT>
__global__ __launch_bounds__(NTH, 2)
void gemm_mma(const bf16* __restrict__ Ahi, const bf16* __restrict__ Whi,
              const float* __restrict__ bias, OutT* __restrict__ C,
              int N, int K, int plain_rows)
{
    int e = GROUPED ? blockIdx.z : 0;
    int nrows = GROUPED ? g_cnt[e] : plain_rows;
    int col0 = blockIdx.y * BN;

    const bf16*  Wh = Whi + (GROUPED ? (size_t)e * N * K : 0);
    const float* bp = bias + (GROUPED ? (size_t)e * N : 0);

    extern __shared__ char smem[];
    int*   srow  = (int*)smem;
    float* sbias = (float*)(smem + 512);
    constexpr int HDR  = 1024;
    constexpr int TILE = BM * 128;

    int t = threadIdx.x;
    if (t < BN) sbias[t] = bp[col0 + t];

    uint32_t sb = smem_u32(smem) + HDR;
    const int lrow = t >> 1, lhalf = (t & 1) * 4, lx7 = lrow & 7;
    const int nc = K >> 6;

    const int wid = t >> 5, lane = t & 31;
    const int wm = (wid & 1) * 64;
    const int wn = (wid >> 1) * 32;
    const int rb = lane & 15, csel = lane >> 4, x7 = rb & 7;
    const int lr4 = lane >> 2, lc2 = 2 * (lane & 3);

    uint32_t arow_b[4], wrow_b[2];
#pragma unroll
    for (int mi = 0; mi < 4; mi++) arow_b[mi] = (wm + mi * 16 + rb) * 128;
#pragma unroll
    for (int nb = 0; nb < 2; nb++) wrow_b[nb] = (wn + nb * 16 + rb) * 128;

    const size_t wrow = (size_t)(col0 + lrow) * K;
    const int ntiles = (nrows + BM - 1) / BM;

    for (int rt = blockIdx.x; rt < ntiles; rt += gridDim.x) {
        int row0 = rt * BM;
        __syncthreads();                 // prior epilogue done reading srow
        if (t < BM) {
            int gr = row0 + t;
            int cr = gr < nrows ? gr : nrows - 1;
            srow[t] = GROUPED ? g_rows[e * B_ + cr] : cr;
        }
        __syncthreads();

        const size_t arow = (size_t)srow[lrow] * K;

        auto stA = [&](int c) { return sb + (uint32_t)(c % 3) * (2 * TILE); };
        auto issueN = [&](int c) {
            uint32_t st = stA(c);
            size_t koff = (size_t)c * 64 + lhalf * 8;
#pragma unroll
            for (int j = 0; j < 4; j++) {
                uint32_t doff = lrow * 128 + (((lhalf + j) ^ lx7) * 16);
                cp16(st + doff, Ahi + arow + koff + j * 8);
                cp16(st + TILE + doff, Wh + wrow + koff + j * 8);
            }
            cp_commit();
        };

        float acc[4][4][4];
#pragma unroll
        for (int i = 0; i < 4; i++)
#pragma unroll
            for (int j = 0; j < 4; j++)
#pragma unroll
                for (int q = 0; q < 4; q++) acc[i][j][q] = 0.0f;

        issueN(0); issueN(1);
        cp_wait<1>();
        __syncthreads();

        for (int c = 0; c < nc; c++) {
            uint32_t st = stA(c);
#pragma unroll
            for (int ks = 0; ks < 4; ks++) {
                uint32_t ksel = (uint32_t)((2 * ks + csel) ^ x7) * 16;
                uint32_t ah[4][4], bh[4][2];
#pragma unroll
                for (int mi = 0; mi < 4; mi++)
                    ldmx4(ah[mi], st + arow_b[mi] + ksel);
#pragma unroll
                for (int nb = 0; nb < 2; nb++) {
                    uint32_t r[4];
                    ldmx4(r, st + TILE + wrow_b[nb] + ksel);
                    bh[2 * nb][0] = r[0]; bh[2 * nb + 1][0] = r[1];
                    bh[2 * nb][1] = r[2]; bh[2 * nb + 1][1] = r[3];
                }
#pragma unroll
                for (int mi = 0; mi < 4; mi++)
#pragma unroll
                    for (int ni = 0; ni < 4; ni++)
                        mma16816(acc[mi][ni], ah[mi], bh[ni]);
            }
            __syncthreads();
            if (c + 2 < nc) issueN(c + 2);
            else            cp_commit();
            cp_wait<1>();
            __syncthreads();
        }
        cp_wait<0>();                    // drain before next iteration reuses stages

        // epilogue
#pragma unroll
        for (int mi = 0; mi < 4; mi++) {
            int r0i = wm + mi * 16 + lr4;
            int r1i = r0i + 8;
            bool v0 = (row0 + r0i) < nrows;
            bool v1 = (row0 + r1i) < nrows;
            size_t g0 = (size_t)srow[r0i] * N + col0;
            size_t g1 = (size_t)srow[r1i] * N + col0;
#pragma unroll
            for (int ni = 0; ni < 4; ni++) {
                int cc = wn + ni * 8 + lc2;
                float ba = sbias[cc], bb = sbias[cc + 1];
                float x0 = acc[mi][ni][0] + ba, x1 = acc[mi][ni][1] + bb;
                float y0 = acc[mi][ni][2] + ba, y1 = acc[mi][ni][3] + bb;
                if (RELU) {
                    x0 = fmaxf(x0, 0.0f); x1 = fmaxf(x1, 0.0f);
                    y0 = fmaxf(y0, 0.0f); y1 = fmaxf(y1, 0.0f);
                }
                if (sizeof(OutT) == 4) {
                    if (v0) *(float2*)((float*)C + g0 + cc) = make_float2(x0, x1);
                    if (v1) *(float2*)((float*)C + g1 + cc) = make_float2(y0, y1);
                } else {
                    uint32_t p0, p1;
                    asm("cvt.rn.bf16x2.f32 %0, %1, %2;" : "=r"(p0) : "f"(x1), "f"(x0));
                    asm("cvt.rn.bf16x2.f32 %0, %1, %2;" : "=r"(p1) : "f"(y1), "f"(y0));
                    if (v0) *(uint32_t*)((bf16*)C + g0 + cc) = p0;
                    if (v1) *(uint32_t*)((bf16*)C + g1 + cc) = p1;
                }
            }
        }
    }
}

// ------- correction GEMM for FLAGGED rows: X1 += qhi@w1lo + qlo@w1hi -----
// Split-K x4 + internal row-tile loop. Grid (8, 4, 4) = 128 CTAs.
__global__ __launch_bounds__(256)
void gemm_flag_k(const bf16* __restrict__ Ahi, const bf16* __restrict__ Alo,
                 const bf16* __restrict__ Whi, const bf16* __restrict__ Wlo,
                 float* __restrict__ C)
{
    int nrows = g_nflag;
    int col0 = blockIdx.y * 128;
    const int c0 = blockIdx.z * 4;     // this CTA's 4 K-chunks

    extern __shared__ char smem[];
    int* srow = (int*)smem;
    constexpr int HDR    = 1024;
    constexpr int T_AHI = 0;
    constexpr int T_ALO = FBM * 128;
    constexpr int T_WHI = 2 * FBM * 128;
    constexpr int T_WLO = 2 * FBM * 128 + 128 * 128;
    constexpr int STAGE = 2 * FBM * 128 + 2 * 128 * 128;

    int t = threadIdx.x;
    uint32_t sb = smem_u32(smem) + HDR;

    const int arw = t >> 3, aj = t & 7, ax7 = arw & 7;
    const int wrw = t >> 1, whalf = (t & 1) * 4, wx7 = wrw & 7;
    const size_t wrow = (size_t)(col0 + wrw) * H_;

    const int wid = t >> 5, lane = t & 31;
    const int wn = wid * 16;
    const int rb = lane & 15, csel = lane >> 4, x7 = rb & 7;
    const int lr4 = lane >> 2, lc2 = 2 * (lane & 3);

    uint32_t arow_b[2];
#pragma unroll
    for (int mi = 0; mi < 2; mi++) arow_b[mi] = (mi * 16 + rb) * 128;
    uint32_t wrow_b = (wn + rb) * 128;

    const int ntiles = (nrows + FBM - 1) / FBM;

    for (int rt = blockIdx.x; rt < ntiles; rt += gridDim.x) {
        int row0 = rt * FBM;
        __syncthreads();
        if (t < FBM) {
            int gr = row0 + t;
            srow[t] = g_flag[gr < nrows ? gr : nrows - 1];
        }
        __syncthreads();

        const size_t arow = (size_t)srow[arw] * H_;

        auto stA = [&](int cc) { return sb + (uint32_t)(cc % 3) * STAGE; };
        auto issue = [&](int cc) {
            uint32_t st = stA(cc);
            size_t koff = (size_t)(c0 + cc) * 64;
            {
                uint32_t doff = arw * 128 + ((aj ^ ax7) * 16);
                cp16(st + T_AHI + doff, Ahi + arow + koff + aj * 8);
                cp16(st + T_ALO + doff, Alo + arow + koff + aj * 8);
            }
#pragma unroll
            for (int j = 0; j < 4; j++) {
                uint32_t doff = wrw * 128 + (((whalf + j) ^ wx7) * 16);
                cp16(st + T_WHI + doff, Whi + wrow + koff + (whalf + j) * 8);
                cp16(st + T_WLO + doff, Wlo + wrow + koff + (whalf + j) * 8);
            }
            cp_commit();
        };

        float acc[2][2][4];
#pragma unroll
        for (int i = 0; i < 2; i++)
#pragma unroll
            for (int j = 0; j < 2; j++)
#pragma unroll
                for (int q = 0; q < 4; q++) acc[i][j][q] = 0.0f;

        issue(0); issue(1);
        cp_wait<1>();
        __syncthreads();

#pragma unroll
        for (int cc = 0; cc < KSPLIT; cc++) {
            uint32_t st = stA(cc);
#pragma unroll
            for (int ks = 0; ks < 4; ks++) {
                uint32_t ksel = (uint32_t)((2 * ks + csel) ^ x7) * 16;
                uint32_t ah[2][4], al[2][4], bh[2][2], bl[2][2];
#pragma unroll
                for (int mi = 0; mi < 2; mi++) {
                    ldmx4(ah[mi], st + T_AHI + arow_b[mi] + ksel);
                    ldmx4(al[mi], st + T_ALO + arow_b[mi] + ksel);
                }
                {
                    uint32_t r[4];
                    ldmx4(r, st + T_WHI + wrow_b + ksel);
                    bh[0][0] = r[0]; bh[1][0] = r[1]; bh[0][1] = r[2]; bh[1][1] = r[3];
                    ldmx4(r, st + T_WLO + wrow_b + ksel);
                    bl[0][0] = r[0]; bl[1][0] = r[1]; bl[0][1] = r[2]; bl[1][1] = r[3];
                }
#pragma unroll
                for (int mi = 0; mi < 2; mi++)
#pragma unroll
                    for (int ni = 0; ni < 2; ni++) {
                        mma16816(acc[mi][ni], ah[mi], bl[ni]);
                        mma16816(acc[mi][ni], al[mi], bh[ni]);
                    }
            }
            __syncthreads();
            if (cc + 2 < KSPLIT) issue(cc + 2);
            else                 cp_commit();
            cp_wait<1>();
            __syncthreads();
        }
        cp_wait<0>();

        // epilogue: atomic accumulate into X1
#pragma unroll
        for (int mi = 0; mi < 2; mi++) {
            int r0i = mi * 16 + lr4;
            int r1i = r0i + 8;
            bool v0 = (row0 + r0i) < nrows;
            bool v1 = (row0 + r1i) < nrows;
            size_t g0 = (size_t)srow[r0i] * HH_ + col0;
            size_t g1 = (size_t)srow[r1i] * HH_ + col0;
#pragma unroll
            for (int ni = 0; ni < 2; ni++) {
                int cc = wn + ni * 8 + lc2;
                if (v0) {
                    atomicAdd(C + g0 + cc,     acc[mi][ni][0]);
                    atomicAdd(C + g0 + cc + 1, acc[mi][ni][1]);
                }
                if (v1) {
                    atomicAdd(C + g1 + cc,     acc[mi][ni][2]);
                    atomicAdd(C + g1 + cc + 1, acc[mi][ni][3]);
                }
            }
        }
    }
}

// --------- logits + argmax; scatter confident rows, flag marginal + qlo ---
__global__ void logits_argmax_kernel(const float* __restrict__ W3,
                                     const float* __restrict__ b3,
                                     const float* __restrict__ q)
{
    __shared__ float sW[M_ * HH_];
    __shared__ float sb[M_];
    for (int i = threadIdx.x; i < M_ * HH_; i += blockDim.x) sW[i] = W3[i];
    if (threadIdx.x < M_) sb[threadIdx.x] = b3[threadIdx.x];
    __syncthreads();

    int gw   = (blockIdx.x * blockDim.x + threadIdx.x) >> 5;
    int lane = threadIdx.x & 31;
    int nw   = (gridDim.x * blockDim.x) >> 5;

    for (int row = gw; row < B_; row += nw) {
        const float* x = g_X1 + (size_t)row * HH_;
        float xv[16];
#pragma unroll
        for (int tt = 0; tt < 16; tt++) xv[tt] = fmaxf(x[lane + 32 * tt], 0.0f);
        float best = -3.0e38f, second = -3.0e38f;
        int   bi   = 0;
#pragma unroll
        for (int m = 0; m < M_; m++) {
            float p = 0.0f;
            const float* wrow = sW + m * HH_;
#pragma unroll
            for (int tt = 0; tt < 16; tt++)
                p = fmaf(xv[tt], wrow[lane + 32 * tt], p);
#pragma unroll
            for (int o = 16; o; o >>= 1) p += __shfl_xor_sync(0xffffffffu, p, o);
            p += sb[m];
            if (p > best) { second = best; best = p; bi = m; }
            else if (p > second) second = p;
        }
        if (best - second >= MARGIN_THRESH) {
            if (lane == 0) {
                int p = atomicAdd(&g_cnt[bi], 1);
                g_rows[bi * B_ + p] = row;
            }
        } else {
            if (lane == 0) {
                int fp = atomicAdd(&g_nflag, 1);
                g_flag[fp] = row;
            }
            const float* src = q + (size_t)row * H_;
            const bf16*  hi  = g_qhi + (size_t)row * H_;
            bf16*        lo  = g_qlo + (size_t)row * H_;
            for (int ii = lane; ii < H_ / 2; ii += 32) {
                float a = src[2 * ii], b = src[2 * ii + 1];
                __nv_bfloat162 h = *(const __nv_bfloat162*)(hi + 2 * ii);
                __nv_bfloat162 l(__float2bfloat16_rn(a - __bfloat162float(h.x)),
                                 __float2bfloat16_rn(b - __bfloat162float(h.y)));
                *(__nv_bfloat162*)(lo + 2 * ii) = l;
            }
        }
    }
}

// --------- exact argmax for flagged rows (X1 now exact pre-relu) ---------
__global__ void logits_fix_kernel(const float* __restrict__ W3,
                                  const float* __restrict__ b3)
{
    __shared__ float sW[M_ * HH_];
    __shared__ float sb[M_];
    for (int i = threadIdx.x; i < M_ * HH_; i += blockDim.x) sW[i] = W3[i];
    if (threadIdx.x < M_) sb[threadIdx.x] = b3[threadIdx.x];
    __syncthreads();

    int gw   = (blockIdx.x * blockDim.x + threadIdx.x) >> 5;
    int lane = threadIdx.x & 31;
    int nw   = (gridDim.x * blockDim.x) >> 5;
    int nf   = g_nflag;

    for (int idx = gw; idx < nf; idx += nw) {
        int row = g_flag[idx];
        const float* x = g_X1 + (size_t)row * HH_;
        float xv[16];
#pragma unroll
        for (int tt = 0; tt < 16; tt++) xv[tt] = fmaxf(x[lane + 32 * tt], 0.0f);
        float best = -3.0e38f;
        int   bi   = 0;
#pragma unroll
        for (int m = 0; m < M_; m++) {
            float p = 0.0f;
            const float* wrow = sW + m * HH_;
#pragma unroll
            for (int tt = 0; tt < 16; tt++)
                p = fmaf(xv[tt], wrow[lane + 32 * tt], p);
#pragma unroll
            for (int o = 16; o; o >>= 1) p += __shfl_xor_sync(0xffffffffu, p, o);
            p += sb[m];
            if (p > best) { best = p; bi = m; }
        }
        if (lane == 0) {
            int p = atomicAdd(&g_cnt[bi], 1);
            g_rows[bi * B_ + p] = row;
        }
    }
}

// out = O/max(||O||,eps) + Q  — one WARP per row, shuffle-only reduction
__global__ void finalize_kernel(const float* __restrict__ Q, float* __restrict__ out)
{
    int wid  = threadIdx.x >> 5;
    int lane = threadIdx.x & 31;
    int row  = blockIdx.x * 8 + wid;

    const bf16* o = g_Ob16 + (size_t)row * H_ + lane * 8;
    float ov[4][8];
#pragma unroll
    for (int seg = 0; seg < 4; seg++) {
        uint4 pk = *(const uint4*)(o + seg * 256);
        const __nv_bfloat162* pp = (const __nv_bfloat162*)&pk;
#pragma unroll
        for (int j = 0; j < 4; j++) {
            ov[seg][2*j]   = __bfloat162float(pp[j].x);
            ov[seg][2*j+1] = __bfloat162float(pp[j].y);
        }
    }

    float s = 0.0f;
#pragma unroll
    for (int seg = 0; seg < 4; seg++)
#pragma unroll
        for (int j = 0; j < 8; j++) s += ov[seg][j] * ov[seg][j];
#pragma unroll
    for (int off = 16; off; off >>= 1) s += __shfl_xor_sync(0xffffffffu, s, off);
    float inv = 1.0f / fmaxf(sqrtf(s), 1e-6f);

    const float* qr = Q + (size_t)row * H_ + lane * 8;
    float* orow = out + (size_t)row * H_ + lane * 8;
#pragma unroll
    for (int seg = 0; seg < 4; seg++) {
        float4 qa = *(const float4*)(qr + seg * 256);
        float4 qb = *(const float4*)(qr + seg * 256 + 4);
        float4 ra, rb;
        ra.x = fmaf(ov[seg][0], inv, qa.x); ra.y = fmaf(ov[seg][1], inv, qa.y);
        ra.z = fmaf(ov[seg][2], inv, qa.z); ra.w = fmaf(ov[seg][3], inv, qa.w);
        rb.x = fmaf(ov[seg][4], inv, qb.x); rb.y = fmaf(ov[seg][5], inv, qb.y);
        rb.z = fmaf(ov[seg][6], inv, qb.z); rb.w = fmaf(ov[seg][7], inv, qb.w);
        *(float4*)(orow + seg * 256)     = ra;
        *(float4*)(orow + seg * 256 + 4) = rb;
    }
}

// ---------------- launch ----------------
extern "C" void kernel_launch(void* const* d_in, const int* in_sizes, int n_in,
                              void* d_out, int out_size)
{
    const float* q   = (const float*)d_in[0];
    const float* c1w = (const float*)d_in[1];
    const float* c1b = (const float*)d_in[2];
    const float* c3w = (const float*)d_in[3];
    const float* c3b = (const float*)d_in[4];
    const float* ew1 = (const float*)d_in[5];
    const float* eb1 = (const float*)d_in[6];
    const float* ew2 = (const float*)d_in[7];
    const float* eb2 = (const float*)d_in[8];
    float* out = (float*)d_out;

    void *pqh, *pql, *pw1h, *pw1l, *pe1, *pe2, *pX1, *pHb, *pO;
    cudaGetSymbolAddress(&pqh,  g_qhi);
    cudaGetSymbolAddress(&pql,  g_qlo);
    cudaGetSymbolAddress(&pw1h, g_w1hi);
    cudaGetSymbolAddress(&pw1l, g_w1lo);
    cudaGetSymbolAddress(&pe1,  g_ew1b);
    cudaGetSymbolAddress(&pe2,  g_ew2b);
    cudaGetSymbolAddress(&pX1,  g_X1);
    cudaGetSymbolAddress(&pHb,  g_Hb);
    cudaGetSymbolAddress(&pO,   g_Ob16);

    constexpr int SMEM_FAST = 1024 + 3 * 2 * BM * 128;                     // 99328
    constexpr int SMEM_FLAG = 1024 + 3 * (2 * FBM * 128 + 2 * 128 * 128);  // 123904

    cudaFuncSetAttribute(gemm_mma<0, 0, float>,
                         cudaFuncAttributeMaxDynamicSharedMemorySize, SMEM_FAST);
    cudaFuncSetAttribute(gemm_flag_k,
                         cudaFuncAttributeMaxDynamicSharedMemorySize, SMEM_FLAG);
    cudaFuncSetAttribute(gemm_mma<1, 1, bf16>,
                         cudaFuncAttributeMaxDynamicSharedMemorySize, SMEM_FAST);
    cudaFuncSetAttribute(gemm_mma<1, 0, bf16>,
                         cudaFuncAttributeMaxDynamicSharedMemorySize, SMEM_FAST);

    // 1) all input conversions + counter zeroing
    {
        long total = (long)B_ * H_ + (long)HH_ * H_ + (long)M_ * HH_ * H_ + (long)M_ * H_ * HH_;
        int grid = (int)((total / 16 + 255) / 256);
        bigcvt_k<<<grid, 256>>>(q, c1w, ew1, ew2);
    }
    // 2) gating hidden (single-pass bf16, PRE-relu): X1 = Q@c1w^T + b
    gemm_mma<0, 0, float><<<dim3(B_ / BM, HH_ / BN, 1), NTH, SMEM_FAST>>>(
        (const bf16*)pqh, (const bf16*)pw1h, c1b, (float*)pX1, HH_, H_, B_);
    // 3) logits + argmax: scatter confident, flag marginal (+ build qlo)
    logits_argmax_kernel<<<64, 256>>>(c3w, c3b, q);
    // 4) correction: X1[flagged] += qhi@w1lo + qlo@w1hi  (split-K x4, 128 CTAs)
    gemm_flag_k<<<dim3(8, HH_ / 128, KSPLIT), 256, SMEM_FLAG>>>(
        (const bf16*)pqh, (const bf16*)pql, (const bf16*)pw1h, (const bf16*)pw1l,
        (float*)pX1);
    // 5) exact argmax + scatter for flagged rows
    logits_fix_kernel<<<32, 256>>>(c3w, c3b);
    // 6) expert hidden: H = relu(Qg @ ew1[m]^T + b1[m])  (256 CTAs, tile loop)
    gemm_mma<1, 1, bf16><<<dim3(4, HH_ / BN, M_), NTH, SMEM_FAST>>>(
        (const bf16*)pqh, (const bf16*)pe1, eb1, (bf16*)pHb, HH_, H_, 0);
    // 7) expert out: O = Hg @ ew2[m]^T + b2[m]  (512 CTAs, tile loop)
    gemm_mma<1, 0, bf16><<<dim3(4, H_ / BN, M_), NTH, SMEM_FAST>>>(
        (const bf16*)pHb, (const bf16*)pe2, eb2, (bf16*)pO, H_, HH_, 0);
    // 8) out = normalize(O) + Q
    finalize_kernel<<<B_ / 8, 256>>>(q, out);
}

// round 15
// speedup vs baseline: 1.2105x; 1.2105x over previous
#include <cuda_runtime.h>
#include <cuda_bf16.h>
#include <cstdint>
#include <math.h>

#define B_  8192
#define H_  1024
#define HH_ 512
#define M_  16
#define BM  128
#define BN  128
#define NTH 256
#define FBM 32
#define KSPLIT 4
#define MARGIN_THRESH 0.03f

typedef __nv_bfloat16 bf16;

// ---------------- scratch (device globals, no allocation) ----------------
__device__ bf16  g_qhi[B_ * H_];
__device__ bf16  g_qlo[B_ * H_];          // filled only for flagged rows
__device__ bf16  g_w1hi[HH_ * H_];
__device__ bf16  g_w1lo[HH_ * H_];
__device__ bf16  g_ew1b[M_ * HH_ * H_];
__device__ bf16  g_ew2b[M_ * H_ * HH_];
__device__ float g_X1[B_ * HH_];          // PRE-relu gating hidden
__device__ bf16  g_Hb[B_ * HH_];
__device__ bf16  g_Ob16[B_ * H_];
__device__ int   g_rows[M_ * B_];
__device__ int   g_cnt[M_];
__device__ int   g_flag[B_];
__device__ int   g_nflag;

// ---------------- PTX helpers ----------------
__device__ __forceinline__ uint32_t smem_u32(const void* p) {
    uint32_t a;
    asm("{ .reg .u64 t; cvta.to.shared.u64 t, %1; cvt.u32.u64 %0, t; }" : "=r"(a) : "l"(p));
    return a;
}
__device__ __forceinline__ void cp16(uint32_t dst, const void* src) {
    asm volatile("cp.async.cg.shared.global [%0], [%1], 16;" :: "r"(dst), "l"(src));
}
__device__ __forceinline__ void cp_commit() { asm volatile("cp.async.commit_group;" ::: "memory"); }
template <int N> __device__ __forceinline__ void cp_wait() {
    asm volatile("cp.async.wait_group %0;" :: "n"(N) : "memory");
}
__device__ __forceinline__ void ldmx4(uint32_t* r, uint32_t addr) {
    asm volatile("ldmatrix.sync.aligned.m8n8.x4.shared.b16 {%0,%1,%2,%3}, [%4];"
                 : "=r"(r[0]), "=r"(r[1]), "=r"(r[2]), "=r"(r[3]) : "r"(addr));
}
__device__ __forceinline__ void mma16816(float* d, const uint32_t* a, const uint32_t* b) {
    asm volatile(
        "mma.sync.aligned.m16n8k16.row.col.f32.bf16.bf16.f32 "
        "{%0,%1,%2,%3}, {%4,%5,%6,%7}, {%8,%9}, {%0,%1,%2,%3};"
        : "+f"(d[0]), "+f"(d[1]), "+f"(d[2]), "+f"(d[3])
        : "r"(a[0]), "r"(a[1]), "r"(a[2]), "r"(a[3]), "r"(b[0]), "r"(b[1]));
}

// ---------------- conversion helpers ----------------
__device__ __forceinline__ void cvt16v(const float* __restrict__ x, bf16* __restrict__ y) {
    float4 v[4];
#pragma unroll
    for (int c = 0; c < 4; c++) v[c] = *(const float4*)(x + c * 4);
    const float* vv = (const float*)v;
    __nv_bfloat162 p[8];
#pragma unroll
    for (int j = 0; j < 8; j++)
        p[j] = __nv_bfloat162(__float2bfloat16_rn(vv[2*j]), __float2bfloat16_rn(vv[2*j+1]));
    *(uint4*)y       = ((uint4*)p)[0];
    *(uint4*)(y + 8) = ((uint4*)p)[1];
}
__device__ __forceinline__ void split16v(const float* __restrict__ x,
                                         bf16* __restrict__ hi, bf16* __restrict__ lo) {
    float4 v[4];
#pragma unroll
    for (int c = 0; c < 4; c++) v[c] = *(const float4*)(x + c * 4);
    const float* vv = (const float*)v;
    __nv_bfloat162 hp[8], lp[8];
#pragma unroll
    for (int j = 0; j < 8; j++) {
        bf16 h0 = __float2bfloat16_rn(vv[2*j]);
        bf16 h1 = __float2bfloat16_rn(vv[2*j+1]);
        hp[j] = __nv_bfloat162(h0, h1);
        lp[j] = __nv_bfloat162(__float2bfloat16_rn(vv[2*j]   - __bfloat162float(h0)),
                               __float2bfloat16_rn(vv[2*j+1] - __bfloat162float(h1)));
    }
    *(uint4*)hi       = ((uint4*)hp)[0];
    *(uint4*)(hi + 8) = ((uint4*)hp)[1];
    *(uint4*)lo       = ((uint4*)lp)[0];
    *(uint4*)(lo + 8) = ((uint4*)lp)[1];
}

__global__ void bigcvt_k(const float* __restrict__ q, const float* __restrict__ c1w,
                         const float* __restrict__ ew1, const float* __restrict__ ew2) {
    if (blockIdx.x == 0) {
        if (threadIdx.x < M_) g_cnt[threadIdx.x] = 0;
        if (threadIdx.x == M_) g_nflag = 0;
    }
    const long N1 = (long)B_ * H_;
    const long N2 = (long)HH_ * H_;
    const long N3 = (long)M_ * HH_ * H_;
    const long N4 = (long)M_ * H_ * HH_;
    long i = ((long)blockIdx.x * blockDim.x + threadIdx.x) * 16;
    if (i < N1)                     cvt16v(q + i, g_qhi + i);
    else if (i < N1 + N2)           split16v(c1w + (i - N1), g_w1hi + (i - N1), g_w1lo + (i - N1));
    else if (i < N1 + N2 + N3)      cvt16v(ew1 + (i - N1 - N2), g_ew1b + (i - N1 - N2));
    else if (i < N1 + N2 + N3 + N4) cvt16v(ew2 + (i - N1 - N2 - N3), g_ew2b + (i - N1 - N2 - N3));
}

// ---------------- main HMMA GEMM (proven R8/R13 config) ----------------
// 256 threads, 128x128 tile, 8 warps of 64x32, 3-stage cp.async pipeline.
// GROUPED: 0 = plain rows, 1 = per-expert (g_rows/g_cnt, blockIdx.z).
template <int GROUPED, int RELU, typename OutT>
__global__ __launch_bounds__(NTH, 2)
void gemm_mma(const bf16* __restrict__ Ahi, const bf16* __restrict__ Whi,
              const float* __restrict__ bias, OutT* __restrict__ C,
              int N, int K, int plain_rows)
{
    int e = GROUPED ? blockIdx.z : 0;
    int nrows = GROUPED ? g_cnt[e] : plain_rows;
    int row0 = blockIdx.x * BM;
    if (row0 >= nrows) return;
    int col0 = blockIdx.y * BN;

    const bf16*  Wh = Whi + (GROUPED ? (size_t)e * N * K : 0);
    const float* bp = bias + (GROUPED ? (size_t)e * N : 0);

    extern __shared__ char smem[];
    int*   srow  = (int*)smem;
    float* sbias = (float*)(smem + 512);
    constexpr int HDR  = 1024;
    constexpr int TILE = BM * 128;

    int t = threadIdx.x;
    if (t < BM) {
        int gr = row0 + t;
        int cr = gr < nrows ? gr : nrows - 1;
        srow[t] = GROUPED ? g_rows[e * B_ + cr] : cr;
    }
    if (t < BN) sbias[t] = bp[col0 + t];
    __syncthreads();

    uint32_t sb = smem_u32(smem) + HDR;

    const int lrow = t >> 1, lhalf = (t & 1) * 4, lx7 = lrow & 7;
    const int nc = K >> 6;
    const size_t arow = (size_t)srow[lrow] * K;
    const size_t wrow = (size_t)(col0 + lrow) * K;

    auto stA = [&](int c) { return sb + (uint32_t)(c % 3) * (2 * TILE); };
    auto issueN = [&](int c) {
        uint32_t st = stA(c);
        size_t koff = (size_t)c * 64 + lhalf * 8;
#pragma unroll
        for (int j = 0; j < 4; j++) {
            uint32_t doff = lrow * 128 + (((lhalf + j) ^ lx7) * 16);
            cp16(st + doff, Ahi + arow + koff + j * 8);
            cp16(st + TILE + doff, Wh + wrow + koff + j * 8);
        }
        cp_commit();
    };

    const int wid = t >> 5, lane = t & 31;
    const int wm = (wid & 1) * 64;
    const int wn = (wid >> 1) * 32;
    const int rb = lane & 15, csel = lane >> 4, x7 = rb & 7;

    float acc[4][4][4];
#pragma unroll
    for (int i = 0; i < 4; i++)
#pragma unroll
        for (int j = 0; j < 4; j++)
#pragma unroll
            for (int q = 0; q < 4; q++) acc[i][j][q] = 0.0f;

    uint32_t arow_b[4], wrow_b[2];
#pragma unroll
    for (int mi = 0; mi < 4; mi++) arow_b[mi] = (wm + mi * 16 + rb) * 128;
#pragma unroll
    for (int nb = 0; nb < 2; nb++) wrow_b[nb] = (wn + nb * 16 + rb) * 128;

    issueN(0); issueN(1);
    cp_wait<1>();
    __syncthreads();

    for (int c = 0; c < nc; c++) {
        uint32_t st = stA(c);
#pragma unroll
        for (int ks = 0; ks < 4; ks++) {
            uint32_t ksel = (uint32_t)((2 * ks + csel) ^ x7) * 16;
            uint32_t ah[4][4], bh[4][2];
#pragma unroll
            for (int mi = 0; mi < 4; mi++)
                ldmx4(ah[mi], st + arow_b[mi] + ksel);
#pragma unroll
            for (int nb = 0; nb < 2; nb++) {
                uint32_t r[4];
                ldmx4(r, st + TILE + wrow_b[nb] + ksel);
                bh[2 * nb][0] = r[0]; bh[2 * nb + 1][0] = r[1];
                bh[2 * nb][1] = r[2]; bh[2 * nb + 1][1] = r[3];
            }
#pragma unroll
            for (int mi = 0; mi < 4; mi++)
#pragma unroll
                for (int ni = 0; ni < 4; ni++)
                    mma16816(acc[mi][ni], ah[mi], bh[ni]);
        }
        __syncthreads();
        if (c + 2 < nc) issueN(c + 2);
        else            cp_commit();
        cp_wait<1>();
        __syncthreads();
    }

    const int lr4 = lane >> 2, lc2 = 2 * (lane & 3);
#pragma unroll
    for (int mi = 0; mi < 4; mi++) {
        int r0i = wm + mi * 16 + lr4;
        int r1i = r0i + 8;
        bool v0 = (row0 + r0i) < nrows;
        bool v1 = (row0 + r1i) < nrows;
        size_t g0 = (size_t)srow[r0i] * N + col0;
        size_t g1 = (size_t)srow[r1i] * N + col0;
#pragma unroll
        for (int ni = 0; ni < 4; ni++) {
            int cc = wn + ni * 8 + lc2;
            float ba = sbias[cc], bb = sbias[cc + 1];
            float x0 = acc[mi][ni][0] + ba, x1 = acc[mi][ni][1] + bb;
            float y0 = acc[mi][ni][2] + ba, y1 = acc[mi][ni][3] + bb;
            if (RELU) {
                x0 = fmaxf(x0, 0.0f); x1 = fmaxf(x1, 0.0f);
                y0 = fmaxf(y0, 0.0f); y1 = fmaxf(y1, 0.0f);
            }
            if (sizeof(OutT) == 4) {
                if (v0) *(float2*)((float*)C + g0 + cc) = make_float2(x0, x1);
                if (v1) *(float2*)((float*)C + g1 + cc) = make_float2(y0, y1);
            } else {
                uint32_t p0, p1;
                asm("cvt.rn.bf16x2.f32 %0, %1, %2;" : "=r"(p0) : "f"(x1), "f"(x0));
                asm("cvt.rn.bf16x2.f32 %0, %1, %2;" : "=r"(p1) : "f"(y1), "f"(y0));
                if (v0) *(uint32_t*)((bf16*)C + g0 + cc) = p0;
                if (v1) *(uint32_t*)((bf16*)C + g1 + cc) = p1;
            }
        }
    }
}

// ------- correction GEMM for FLAGGED rows: X1 += qhi@w1lo + qlo@w1hi -----
// Split-K x4 + internal row-tile loop. Grid (8, 4, 4) = 128 CTAs. (R14 win.)
__global__ __launch_bounds__(256)
void gemm_flag_k(const bf16* __restrict__ Ahi, const bf16* __restrict__ Alo,
                 const bf16* __restrict__ Whi, const bf16* __restrict__ Wlo,
                 float* __restrict__ C)
{
    int nrows = g_nflag;
    int col0 = blockIdx.y * 128;
    const int c0 = blockIdx.z * 4;     // this CTA's 4 K-chunks

    extern __shared__ char smem[];
    int* srow = (int*)smem;
    constexpr int HDR    = 1024;
    constexpr int T_AHI = 0;
    constexpr int T_ALO = FBM * 128;
    constexpr int T_WHI = 2 * FBM * 128;
    constexpr int T_WLO = 2 * FBM * 128 + 128 * 128;
    constexpr int STAGE = 2 * FBM * 128 + 2 * 128 * 128;

    int t = threadIdx.x;
    uint32_t sb = smem_u32(smem) + HDR;

    const int arw = t >> 3, aj = t & 7, ax7 = arw & 7;
    const int wrw = t >> 1, whalf = (t & 1) * 4, wx7 = wrw & 7;
    const size_t wrow = (size_t)(col0 + wrw) * H_;

    const int wid = t >> 5, lane = t & 31;
    const int wn = wid * 16;
    const int rb = lane & 15, csel = lane >> 4, x7 = rb & 7;
    const int lr4 = lane >> 2, lc2 = 2 * (lane & 3);

    uint32_t arow_b[2];
#pragma unroll
    for (int mi = 0; mi < 2; mi++) arow_b[mi] = (mi * 16 + rb) * 128;
    uint32_t wrow_b = (wn + rb) * 128;

    const int ntiles = (nrows + FBM - 1) / FBM;

    for (int rt = blockIdx.x; rt < ntiles; rt += gridDim.x) {
        int row0 = rt * FBM;
        __syncthreads();
        if (t < FBM) {
            int gr = row0 + t;
            srow[t] = g_flag[gr < nrows ? gr : nrows - 1];
        }
        __syncthreads();

        const size_t arow = (size_t)srow[arw] * H_;

        auto stA = [&](int cc) { return sb + (uint32_t)(cc % 3) * STAGE; };
        auto issue = [&](int cc) {
            uint32_t st = stA(cc);
            size_t koff = (size_t)(c0 + cc) * 64;
            {
                uint32_t doff = arw * 128 + ((aj ^ ax7) * 16);
                cp16(st + T_AHI + doff, Ahi + arow + koff + aj * 8);
                cp16(st + T_ALO + doff, Alo + arow + koff + aj * 8);
            }
#pragma unroll
            for (int j = 0; j < 4; j++) {
                uint32_t doff = wrw * 128 + (((whalf + j) ^ wx7) * 16);
                cp16(st + T_WHI + doff, Whi + wrow + koff + (whalf + j) * 8);
                cp16(st + T_WLO + doff, Wlo + wrow + koff + (whalf + j) * 8);
            }
            cp_commit();
        };

        float acc[2][2][4];
#pragma unroll
        for (int i = 0; i < 2; i++)
#pragma unroll
            for (int j = 0; j < 2; j++)
#pragma unroll
                for (int q = 0; q < 4; q++) acc[i][j][q] = 0.0f;

        issue(0); issue(1);
        cp_wait<1>();
        __syncthreads();

#pragma unroll
        for (int cc = 0; cc < KSPLIT; cc++) {
            uint32_t st = stA(cc);
#pragma unroll
            for (int ks = 0; ks < 4; ks++) {
                uint32_t ksel = (uint32_t)((2 * ks + csel) ^ x7) * 16;
                uint32_t ah[2][4], al[2][4], bh[2][2], bl[2][2];
#pragma unroll
                for (int mi = 0; mi < 2; mi++) {
                    ldmx4(ah[mi], st + T_AHI + arow_b[mi] + ksel);
                    ldmx4(al[mi], st + T_ALO + arow_b[mi] + ksel);
                }
                {
                    uint32_t r[4];
                    ldmx4(r, st + T_WHI + wrow_b + ksel);
                    bh[0][0] = r[0]; bh[1][0] = r[1]; bh[0][1] = r[2]; bh[1][1] = r[3];
                    ldmx4(r, st + T_WLO + wrow_b + ksel);
                    bl[0][0] = r[0]; bl[1][0] = r[1]; bl[0][1] = r[2]; bl[1][1] = r[3];
                }
#pragma unroll
                for (int mi = 0; mi < 2; mi++)
#pragma unroll
                    for (int ni = 0; ni < 2; ni++) {
                        mma16816(acc[mi][ni], ah[mi], bl[ni]);   // qhi @ w1lo
                        mma16816(acc[mi][ni], al[mi], bh[ni]);   // qlo @ w1hi
                    }
            }
            __syncthreads();
            if (cc + 2 < KSPLIT) issue(cc + 2);
            else                 cp_commit();
            cp_wait<1>();
            __syncthreads();
        }
        cp_wait<0>();

        // epilogue: atomic accumulate into X1
#pragma unroll
        for (int mi = 0; mi < 2; mi++) {
            int r0i = mi * 16 + lr4;
            int r1i = r0i + 8;
            bool v0 = (row0 + r0i) < nrows;
            bool v1 = (row0 + r1i) < nrows;
            size_t g0 = (size_t)srow[r0i] * HH_ + col0;
            size_t g1 = (size_t)srow[r1i] * HH_ + col0;
#pragma unroll
            for (int ni = 0; ni < 2; ni++) {
                int cc = wn + ni * 8 + lc2;
                if (v0) {
                    atomicAdd(C + g0 + cc,     acc[mi][ni][0]);
                    atomicAdd(C + g0 + cc + 1, acc[mi][ni][1]);
                }
                if (v1) {
                    atomicAdd(C + g1 + cc,     acc[mi][ni][2]);
                    atomicAdd(C + g1 + cc + 1, acc[mi][ni][3]);
                }
            }
        }
    }
}

// --------- logits + argmax; scatter confident rows, flag marginal + qlo ---
__global__ void logits_argmax_kernel(const float* __restrict__ W3,
                                     const float* __restrict__ b3,
                                     const float* __restrict__ q)
{
    __shared__ float sW[M_ * HH_];
    __shared__ float sb[M_];
    for (int i = threadIdx.x; i < M_ * HH_; i += blockDim.x) sW[i] = W3[i];
    if (threadIdx.x < M_) sb[threadIdx.x] = b3[threadIdx.x];
    __syncthreads();

    int gw   = (blockIdx.x * blockDim.x + threadIdx.x) >> 5;
    int lane = threadIdx.x & 31;
    int nw   = (gridDim.x * blockDim.x) >> 5;

    for (int row = gw; row < B_; row += nw) {
        const float* x = g_X1 + (size_t)row * HH_;
        float xv[16];
#pragma unroll
        for (int tt = 0; tt < 16; tt++) xv[tt] = fmaxf(x[lane + 32 * tt], 0.0f);
        float best = -3.0e38f, second = -3.0e38f;
        int   bi   = 0;
#pragma unroll
        for (int m = 0; m < M_; m++) {
            float p = 0.0f;
            const float* wrow = sW + m * HH_;
#pragma unroll
            for (int tt = 0; tt < 16; tt++)
                p = fmaf(xv[tt], wrow[lane + 32 * tt], p);
#pragma unroll
            for (int o = 16; o; o >>= 1) p += __shfl_xor_sync(0xffffffffu, p, o);
            p += sb[m];
            if (p > best) { second = best; best = p; bi = m; }
            else if (p > second) second = p;
        }
        if (best - second >= MARGIN_THRESH) {
            if (lane == 0) {
                int p = atomicAdd(&g_cnt[bi], 1);
                g_rows[bi * B_ + p] = row;
            }
        } else {
            if (lane == 0) {
                int fp = atomicAdd(&g_nflag, 1);
                g_flag[fp] = row;
            }
            const float* src = q + (size_t)row * H_;
            const bf16*  hi  = g_qhi + (size_t)row * H_;
            bf16*        lo  = g_qlo + (size_t)row * H_;
            for (int ii = lane; ii < H_ / 2; ii += 32) {
                float a = src[2 * ii], b = src[2 * ii + 1];
                __nv_bfloat162 h = *(const __nv_bfloat162*)(hi + 2 * ii);
                __nv_bfloat162 l(__float2bfloat16_rn(a - __bfloat162float(h.x)),
                                 __float2bfloat16_rn(b - __bfloat162float(h.y)));
                *(__nv_bfloat162*)(lo + 2 * ii) = l;
            }
        }
    }
}

// --------- exact argmax for flagged rows (X1 now exact pre-relu) ---------
__global__ void logits_fix_kernel(const float* __restrict__ W3,
                                  const float* __restrict__ b3)
{
    __shared__ float sW[M_ * HH_];
    __shared__ float sb[M_];
    for (int i = threadIdx.x; i < M_ * HH_; i += blockDim.x) sW[i] = W3[i];
    if (threadIdx.x < M_) sb[threadIdx.x] = b3[threadIdx.x];
    __syncthreads();

    int gw   = (blockIdx.x * blockDim.x + threadIdx.x) >> 5;
    int lane = threadIdx.x & 31;
    int nw   = (gridDim.x * blockDim.x) >> 5;
    int nf   = g_nflag;

    for (int idx = gw; idx < nf; idx += nw) {
        int row = g_flag[idx];
        const float* x = g_X1 + (size_t)row * HH_;
        float xv[16];
#pragma unroll
        for (int tt = 0; tt < 16; tt++) xv[tt] = fmaxf(x[lane + 32 * tt], 0.0f);
        float best = -3.0e38f;
        int   bi   = 0;
#pragma unroll
        for (int m = 0; m < M_; m++) {
            float p = 0.0f;
            const float* wrow = sW + m * HH_;
#pragma unroll
            for (int tt = 0; tt < 16; tt++)
                p = fmaf(xv[tt], wrow[lane + 32 * tt], p);
#pragma unroll
            for (int o = 16; o; o >>= 1) p += __shfl_xor_sync(0xffffffffu, p, o);
            p += sb[m];
            if (p > best) { best = p; bi = m; }
        }
        if (lane == 0) {
            int p = atomicAdd(&g_cnt[bi], 1);
            g_rows[bi * B_ + p] = row;
        }
    }
}

// out = O/max(||O||,eps) + Q  — one WARP per row, shuffle-only reduction
__global__ void finalize_kernel(const float* __restrict__ Q, float* __restrict__ out)
{
    int wid  = threadIdx.x >> 5;
    int lane = threadIdx.x & 31;
    int row  = blockIdx.x * 8 + wid;

    const bf16* o = g_Ob16 + (size_t)row * H_ + lane * 8;
    float ov[4][8];
#pragma unroll
    for (int seg = 0; seg < 4; seg++) {
        uint4 pk = *(const uint4*)(o + seg * 256);
        const __nv_bfloat162* pp = (const __nv_bfloat162*)&pk;
#pragma unroll
        for (int j = 0; j < 4; j++) {
            ov[seg][2*j]   = __bfloat162float(pp[j].x);
            ov[seg][2*j+1] = __bfloat162float(pp[j].y);
        }
    }

    float s = 0.0f;
#pragma unroll
    for (int seg = 0; seg < 4; seg++)
#pragma unroll
        for (int j = 0; j < 8; j++) s += ov[seg][j] * ov[seg][j];
#pragma unroll
    for (int off = 16; off; off >>= 1) s += __shfl_xor_sync(0xffffffffu, s, off);
    float inv = 1.0f / fmaxf(sqrtf(s), 1e-6f);

    const float* qr = Q + (size_t)row * H_ + lane * 8;
    float* orow = out + (size_t)row * H_ + lane * 8;
#pragma unroll
    for (int seg = 0; seg < 4; seg++) {
        float4 qa = *(const float4*)(qr + seg * 256);
        float4 qb = *(const float4*)(qr + seg * 256 + 4);
        float4 ra, rb;
        ra.x = fmaf(ov[seg][0], inv, qa.x); ra.y = fmaf(ov[seg][1], inv, qa.y);
        ra.z = fmaf(ov[seg][2], inv, qa.z); ra.w = fmaf(ov[seg][3], inv, qa.w);
        rb.x = fmaf(ov[seg][4], inv, qb.x); rb.y = fmaf(ov[seg][5], inv, qb.y);
        rb.z = fmaf(ov[seg][6], inv, qb.z); rb.w = fmaf(ov[seg][7], inv, qb.w);
        *(float4*)(orow + seg * 256)     = ra;
        *(float4*)(orow + seg * 256 + 4) = rb;
    }
}

// ---------------- launch ----------------
extern "C" void kernel_launch(void* const* d_in, const int* in_sizes, int n_in,
                              void* d_out, int out_size)
{
    const float* q   = (const float*)d_in[0];
    const float* c1w = (const float*)d_in[1];
    const float* c1b = (const float*)d_in[2];
    const float* c3w = (const float*)d_in[3];
    const float* c3b = (const float*)d_in[4];
    const float* ew1 = (const float*)d_in[5];
    const float* eb1 = (const float*)d_in[6];
    const float* ew2 = (const float*)d_in[7];
    const float* eb2 = (const float*)d_in[8];
    float* out = (float*)d_out;

    void *pqh, *pql, *pw1h, *pw1l, *pe1, *pe2, *pX1, *pHb, *pO;
    cudaGetSymbolAddress(&pqh,  g_qhi);
    cudaGetSymbolAddress(&pql,  g_qlo);
    cudaGetSymbolAddress(&pw1h, g_w1hi);
    cudaGetSymbolAddress(&pw1l, g_w1lo);
    cudaGetSymbolAddress(&pe1,  g_ew1b);
    cudaGetSymbolAddress(&pe2,  g_ew2b);
    cudaGetSymbolAddress(&pX1,  g_X1);
    cudaGetSymbolAddress(&pHb,  g_Hb);
    cudaGetSymbolAddress(&pO,   g_Ob16);

    constexpr int SMEM_FAST = 1024 + 3 * 2 * BM * 128;                     // 99328
    constexpr int SMEM_FLAG = 1024 + 3 * (2 * FBM * 128 + 2 * 128 * 128);  // 123904

    cudaFuncSetAttribute(gemm_mma<0, 0, float>,
                         cudaFuncAttributeMaxDynamicSharedMemorySize, SMEM_FAST);
    cudaFuncSetAttribute(gemm_flag_k,
                         cudaFuncAttributeMaxDynamicSharedMemorySize, SMEM_FLAG);
    cudaFuncSetAttribute(gemm_mma<1, 1, bf16>,
                         cudaFuncAttributeMaxDynamicSharedMemorySize, SMEM_FAST);
    cudaFuncSetAttribute(gemm_mma<1, 0, bf16>,
                         cudaFuncAttributeMaxDynamicSharedMemorySize, SMEM_FAST);

    // 1) all input conversions + counter zeroing
    {
        long total = (long)B_ * H_ + (long)HH_ * H_ + (long)M_ * HH_ * H_ + (long)M_ * H_ * HH_;
        int grid = (int)((total / 16 + 255) / 256);
        bigcvt_k<<<grid, 256>>>(q, c1w, ew1, ew2);
    }
    // 2) gating hidden (single-pass bf16, PRE-relu): X1 = Q@c1w^T + b
    gemm_mma<0, 0, float><<<dim3(B_ / BM, HH_ / BN, 1), NTH, SMEM_FAST>>>(
        (const bf16*)pqh, (const bf16*)pw1h, c1b, (float*)pX1, HH_, H_, B_);
    // 3) logits + argmax: scatter confident, flag marginal (+ build qlo)
    logits_argmax_kernel<<<64, 256>>>(c3w, c3b, q);
    // 4) correction: X1[flagged] += qhi@w1lo + qlo@w1hi  (split-K x4, 128 CTAs)
    gemm_flag_k<<<dim3(8, HH_ / 128, KSPLIT), 256, SMEM_FLAG>>>(
        (const bf16*)pqh, (const bf16*)pql, (const bf16*)pw1h, (const bf16*)pw1l,
        (float*)pX1);
    // 5) exact argmax + scatter for flagged rows
    logits_fix_kernel<<<32, 256>>>(c3w, c3b);
    // 6) expert hidden: H = relu(Qg @ ew1[m]^T + b1[m])  (full grid, bf16 out)
    gemm_mma<1, 1, bf16><<<dim3(B_ / BM, HH_ / BN, M_), NTH, SMEM_FAST>>>(
        (const bf16*)pqh, (const bf16*)pe1, eb1, (bf16*)pHb, HH_, H_, 0);
    // 7) expert out: O = Hg @ ew2[m]^T + b2[m]  (full grid, bf16 out)
    gemm_mma<1, 0, bf16><<<dim3(B_ / BM, H_ / BN, M_), NTH, SMEM_FAST>>>(
        (const bf16*)pHb, (const bf16*)pe2, eb2, (bf16*)pO, H_, HH_, 0);
    // 8) out = normalize(O) + Q
    finalize_kernel<<<B_ / 8, 256>>>(q, out);
}

// round 16
// speedup vs baseline: 1.4170x; 1.1705x over previous
#include <cuda_runtime.h>
#include <cuda_bf16.h>
#include <cstdint>
#include <math.h>

#define B_  8192
#define H_  1024
#define HH_ 512
#define M_  16
#define BM  128
#define BN  128
#define NTH 256
#define FBM 32
#define KSPLIT 8
#define FCHUNKS (16 / KSPLIT)
#define MARGIN_THRESH 0.03f

typedef __nv_bfloat16 bf16;

// ---------------- scratch (device globals, no allocation) ----------------
__device__ bf16  g_qhi[B_ * H_];
__device__ bf16  g_qlo[B_ * H_];          // filled only for flagged rows
__device__ bf16  g_w1hi[HH_ * H_];
__device__ bf16  g_w1lo[HH_ * H_];
__device__ bf16  g_ew1b[M_ * HH_ * H_];
__device__ bf16  g_ew2b[M_ * H_ * HH_];
__device__ float g_X1[B_ * HH_];          // PRE-relu gating hidden
__device__ bf16  g_Hb[B_ * HH_];
__device__ bf16  g_Ob16[B_ * H_];
__device__ int   g_rows[M_ * B_];
__device__ int   g_cnt[M_];
__device__ int   g_flag[B_];
__device__ int   g_nflag;

// ---------------- PTX helpers ----------------
__device__ __forceinline__ uint32_t smem_u32(const void* p) {
    uint32_t a;
    asm("{ .reg .u64 t; cvta.to.shared.u64 t, %1; cvt.u32.u64 %0, t; }" : "=r"(a) : "l"(p));
    return a;
}
__device__ __forceinline__ void cp16(uint32_t dst, const void* src) {
    asm volatile("cp.async.cg.shared.global [%0], [%1], 16;" :: "r"(dst), "l"(src));
}
__device__ __forceinline__ void cp_commit() { asm volatile("cp.async.commit_group;" ::: "memory"); }
template <int N> __device__ __forceinline__ void cp_wait() {
    asm volatile("cp.async.wait_group %0;" :: "n"(N) : "memory");
}
__device__ __forceinline__ void ldmx4(uint32_t* r, uint32_t addr) {
    asm volatile("ldmatrix.sync.aligned.m8n8.x4.shared.b16 {%0,%1,%2,%3}, [%4];"
                 : "=r"(r[0]), "=r"(r[1]), "=r"(r[2]), "=r"(r[3]) : "r"(addr));
}
__device__ __forceinline__ void mma16816(float* d, const uint32_t* a, const uint32_t* b) {
    asm volatile(
        "mma.sync.aligned.m16n8k16.row.col.f32.bf16.bf16.f32 "
        "{%0,%1,%2,%3}, {%4,%5,%6,%7}, {%8,%9}, {%0,%1,%2,%3};"
        : "+f"(d[0]), "+f"(d[1]), "+f"(d[2]), "+f"(d[3])
        : "r"(a[0]), "r"(a[1]), "r"(a[2]), "r"(a[3]), "r"(b[0]), "r"(b[1]));
}

// ---------------- conversion helpers ----------------
__device__ __forceinline__ void cvt16v(const float* __restrict__ x, bf16* __restrict__ y) {
    float4 v[4];
#pragma unroll
    for (int c = 0; c < 4; c++) v[c] = *(const float4*)(x + c * 4);
    const float* vv = (const float*)v;
    __nv_bfloat162 p[8];
#pragma unroll
    for (int j = 0; j < 8; j++)
        p[j] = __nv_bfloat162(__float2bfloat16_rn(vv[2*j]), __float2bfloat16_rn(vv[2*j+1]));
    *(uint4*)y       = ((uint4*)p)[0];
    *(uint4*)(y + 8) = ((uint4*)p)[1];
}
__device__ __forceinline__ void split16v(const float* __restrict__ x,
                                         bf16* __restrict__ hi, bf16* __restrict__ lo) {
    float4 v[4];
#pragma unroll
    for (int c = 0; c < 4; c++) v[c] = *(const float4*)(x + c * 4);
    const float* vv = (const float*)v;
    __nv_bfloat162 hp[8], lp[8];
#pragma unroll
    for (int j = 0; j < 8; j++) {
        bf16 h0 = __float2bfloat16_rn(vv[2*j]);
        bf16 h1 = __float2bfloat16_rn(vv[2*j+1]);
        hp[j] = __nv_bfloat162(h0, h1);
        lp[j] = __nv_bfloat162(__float2bfloat16_rn(vv[2*j]   - __bfloat162float(h0)),
                               __float2bfloat16_rn(vv[2*j+1] - __bfloat162float(h1)));
    }
    *(uint4*)hi       = ((uint4*)hp)[0];
    *(uint4*)(hi + 8) = ((uint4*)hp)[1];
    *(uint4*)lo       = ((uint4*)lp)[0];
    *(uint4*)(lo + 8) = ((uint4*)lp)[1];
}

// one conversion worker processes a 16-elem block (segments all divisible by 32)
__device__ __forceinline__ void cvt_block16(long i, const float* __restrict__ q,
                                            const float* __restrict__ c1w,
                                            const float* __restrict__ ew1,
                                            const float* __restrict__ ew2) {
    const long N1 = (long)B_ * H_;
    const long N2 = (long)HH_ * H_;
    const long N3 = (long)M_ * HH_ * H_;
    const long N4 = (long)M_ * H_ * HH_;
    if (i < N1)                     cvt16v(q + i, g_qhi + i);
    else if (i < N1 + N2)           split16v(c1w + (i - N1), g_w1hi + (i - N1), g_w1lo + (i - N1));
    else if (i < N1 + N2 + N3)      cvt16v(ew1 + (i - N1 - N2), g_ew1b + (i - N1 - N2));
    else if (i < N1 + N2 + N3 + N4) cvt16v(ew2 + (i - N1 - N2 - N3), g_ew2b + (i - N1 - N2 - N3));
}

__global__ void bigcvt_k(const float* __restrict__ q, const float* __restrict__ c1w,
                         const float* __restrict__ ew1, const float* __restrict__ ew2) {
    if (blockIdx.x == 0) {
        if (threadIdx.x < M_) g_cnt[threadIdx.x] = 0;
        if (threadIdx.x == M_) g_nflag = 0;
    }
    long i = ((long)blockIdx.x * blockDim.x + threadIdx.x) * 32;
    cvt_block16(i, q, c1w, ew1, ew2);
    cvt_block16(i + 16, q, c1w, ew1, ew2);
}

// ---------------- main HMMA GEMM (proven engine, 1 barrier/chunk) --------
// 256 threads, 128x128 tile, 8 warps of 64x32, 3-stage cp.async pipeline.
// GROUPED: 0 = plain rows, 1 = per-expert (g_rows/g_cnt, blockIdx.z).
template <int GROUPED, int RELU, typename OutT>
__global__ __launch_bounds__(NTH, 2)
void gemm_mma(const bf16* __restrict__ Ahi, const bf16* __restrict__ Whi,
              const float* __restrict__ bias, OutT* __restrict__ C,
              int N, int K, int plain_rows)
{
    int e = GROUPED ? blockIdx.z : 0;
    int nrows = GROUPED ? g_cnt[e] : plain_rows;
    int row0 = blockIdx.x * BM;
    if (row0 >= nrows) return;
    int col0 = blockIdx.y * BN;

    const bf16*  Wh = Whi + (GROUPED ? (size_t)e * N * K : 0);
    const float* bp = bias + (GROUPED ? (size_t)e * N : 0);

    extern __shared__ char smem[];
    int*   srow  = (int*)smem;
    float* sbias = (float*)(smem + 512);
    constexpr int HDR  = 1024;
    constexpr int TILE = BM * 128;

    int t = threadIdx.x;
    if (t < BM) {
        int gr = row0 + t;
        int cr = gr < nrows ? gr : nrows - 1;
        srow[t] = GROUPED ? g_rows[e * B_ + cr] : cr;
    }
    if (t < BN) sbias[t] = bp[col0 + t];
    __syncthreads();

    uint32_t sb = smem_u32(smem) + HDR;

    const int lrow = t >> 1, lhalf = (t & 1) * 4, lx7 = lrow & 7;
    const int nc = K >> 6;
    const size_t arow = (size_t)srow[lrow] * K;
    const size_t wrow = (size_t)(col0 + lrow) * K;

    auto stA = [&](int c) { return sb + (uint32_t)(c % 3) * (2 * TILE); };
    auto issueN = [&](int c) {
        uint32_t st = stA(c);
        size_t koff = (size_t)c * 64 + lhalf * 8;
#pragma unroll
        for (int j = 0; j < 4; j++) {
            uint32_t doff = lrow * 128 + (((lhalf + j) ^ lx7) * 16);
            cp16(st + doff, Ahi + arow + koff + j * 8);
            cp16(st + TILE + doff, Wh + wrow + koff + j * 8);
        }
        cp_commit();
    };

    const int wid = t >> 5, lane = t & 31;
    const int wm = (wid & 1) * 64;
    const int wn = (wid >> 1) * 32;
    const int rb = lane & 15, csel = lane >> 4, x7 = rb & 7;

    float acc[4][4][4];
#pragma unroll
    for (int i = 0; i < 4; i++)
#pragma unroll
        for (int j = 0; j < 4; j++)
#pragma unroll
            for (int q = 0; q < 4; q++) acc[i][j][q] = 0.0f;

    uint32_t arow_b[4], wrow_b[2];
#pragma unroll
    for (int mi = 0; mi < 4; mi++) arow_b[mi] = (wm + mi * 16 + rb) * 128;
#pragma unroll
    for (int nb = 0; nb < 2; nb++) wrow_b[nb] = (wn + nb * 16 + rb) * 128;

    issueN(0); issueN(1);
    cp_wait<1>();
    __syncthreads();

    for (int c = 0; c < nc; c++) {
        uint32_t st = stA(c);
#pragma unroll
        for (int ks = 0; ks < 4; ks++) {
            uint32_t ksel = (uint32_t)((2 * ks + csel) ^ x7) * 16;
            uint32_t ah[4][4], bh[4][2];
#pragma unroll
            for (int mi = 0; mi < 4; mi++)
                ldmx4(ah[mi], st + arow_b[mi] + ksel);
#pragma unroll
            for (int nb = 0; nb < 2; nb++) {
                uint32_t r[4];
                ldmx4(r, st + TILE + wrow_b[nb] + ksel);
                bh[2 * nb][0] = r[0]; bh[2 * nb + 1][0] = r[1];
                bh[2 * nb][1] = r[2]; bh[2 * nb + 1][1] = r[3];
            }
#pragma unroll
            for (int mi = 0; mi < 4; mi++)
#pragma unroll
                for (int ni = 0; ni < 4; ni++)
                    mma16816(acc[mi][ni], ah[mi], bh[ni]);
        }
        // single barrier per chunk: all reads of stage (c-1)%3 happened before
        // the PREVIOUS barrier, so issuing into it here is safe.
        if (c + 2 < nc) issueN(c + 2);
        else            cp_commit();
        cp_wait<1>();
        __syncthreads();
    }

    const int lr4 = lane >> 2, lc2 = 2 * (lane & 3);
#pragma unroll
    for (int mi = 0; mi < 4; mi++) {
        int r0i = wm + mi * 16 + lr4;
        int r1i = r0i + 8;
        bool v0 = (row0 + r0i) < nrows;
        bool v1 = (row0 + r1i) < nrows;
        size_t g0 = (size_t)srow[r0i] * N + col0;
        size_t g1 = (size_t)srow[r1i] * N + col0;
#pragma unroll
        for (int ni = 0; ni < 4; ni++) {
            int cc = wn + ni * 8 + lc2;
            float ba = sbias[cc], bb = sbias[cc + 1];
            float x0 = acc[mi][ni][0] + ba, x1 = acc[mi][ni][1] + bb;
            float y0 = acc[mi][ni][2] + ba, y1 = acc[mi][ni][3] + bb;
            if (RELU) {
                x0 = fmaxf(x0, 0.0f); x1 = fmaxf(x1, 0.0f);
                y0 = fmaxf(y0, 0.0f); y1 = fmaxf(y1, 0.0f);
            }
            if (sizeof(OutT) == 4) {
                if (v0) *(float2*)((float*)C + g0 + cc) = make_float2(x0, x1);
                if (v1) *(float2*)((float*)C + g1 + cc) = make_float2(y0, y1);
            } else {
                uint32_t p0, p1;
                asm("cvt.rn.bf16x2.f32 %0, %1, %2;" : "=r"(p0) : "f"(x1), "f"(x0));
                asm("cvt.rn.bf16x2.f32 %0, %1, %2;" : "=r"(p1) : "f"(y1), "f"(y0));
                if (v0) *(uint32_t*)((bf16*)C + g0 + cc) = p0;
                if (v1) *(uint32_t*)((bf16*)C + g1 + cc) = p1;
            }
        }
    }
}

// ------- correction GEMM for FLAGGED rows: X1 += qhi@w1lo + qlo@w1hi -----
// Split-K x8 (2 chunks/CTA) + internal row-tile loop. Grid (8,4,8) = 256 CTAs.
__global__ __launch_bounds__(256)
void gemm_flag_k(const bf16* __restrict__ Ahi, const bf16* __restrict__ Alo,
                 const bf16* __restrict__ Whi, const bf16* __restrict__ Wlo,
                 float* __restrict__ C)
{
    int nrows = g_nflag;
    int col0 = blockIdx.y * 128;
    const int c0 = blockIdx.z * FCHUNKS;   // this CTA's K-chunks

    extern __shared__ char smem[];
    int* srow = (int*)smem;
    constexpr int HDR    = 1024;
    constexpr int T_AHI = 0;
    constexpr int T_ALO = FBM * 128;
    constexpr int T_WHI = 2 * FBM * 128;
    constexpr int T_WLO = 2 * FBM * 128 + 128 * 128;
    constexpr int STAGE = 2 * FBM * 128 + 2 * 128 * 128;

    int t = threadIdx.x;
    uint32_t sb = smem_u32(smem) + HDR;

    const int arw = t >> 3, aj = t & 7, ax7 = arw & 7;
    const int wrw = t >> 1, whalf = (t & 1) * 4, wx7 = wrw & 7;
    const size_t wrow = (size_t)(col0 + wrw) * H_;

    const int wid = t >> 5, lane = t & 31;
    const int wn = wid * 16;
    const int rb = lane & 15, csel = lane >> 4, x7 = rb & 7;
    const int lr4 = lane >> 2, lc2 = 2 * (lane & 3);

    uint32_t arow_b[2];
#pragma unroll
    for (int mi = 0; mi < 2; mi++) arow_b[mi] = (mi * 16 + rb) * 128;
    uint32_t wrow_b = (wn + rb) * 128;

    const int ntiles = (nrows + FBM - 1) / FBM;

    for (int rt = blockIdx.x; rt < ntiles; rt += gridDim.x) {
        int row0 = rt * FBM;
        __syncthreads();
        if (t < FBM) {
            int gr = row0 + t;
            srow[t] = g_flag[gr < nrows ? gr : nrows - 1];
        }
        __syncthreads();

        const size_t arow = (size_t)srow[arw] * H_;

        auto stA = [&](int cc) { return sb + (uint32_t)(cc % 3) * STAGE; };
        auto issue = [&](int cc) {
            uint32_t st = stA(cc);
            size_t koff = (size_t)(c0 + cc) * 64;
            {
                uint32_t doff = arw * 128 + ((aj ^ ax7) * 16);
                cp16(st + T_AHI + doff, Ahi + arow + koff + aj * 8);
                cp16(st + T_ALO + doff, Alo + arow + koff + aj * 8);
            }
#pragma unroll
            for (int j = 0; j < 4; j++) {
                uint32_t doff = wrw * 128 + (((whalf + j) ^ wx7) * 16);
                cp16(st + T_WHI + doff, Whi + wrow + koff + (whalf + j) * 8);
                cp16(st + T_WLO + doff, Wlo + wrow + koff + (whalf + j) * 8);
            }
            cp_commit();
        };

        float acc[2][2][4];
#pragma unroll
        for (int i = 0; i < 2; i++)
#pragma unroll
            for (int j = 0; j < 2; j++)
#pragma unroll
                for (int q = 0; q < 4; q++) acc[i][j][q] = 0.0f;

        issue(0); issue(1);
        cp_wait<1>();
        __syncthreads();

#pragma unroll
        for (int cc = 0; cc < FCHUNKS; cc++) {
            uint32_t st = stA(cc);
#pragma unroll
            for (int ks = 0; ks < 4; ks++) {
                uint32_t ksel = (uint32_t)((2 * ks + csel) ^ x7) * 16;
                uint32_t ah[2][4], al[2][4], bh[2][2], bl[2][2];
#pragma unroll
                for (int mi = 0; mi < 2; mi++) {
                    ldmx4(ah[mi], st + T_AHI + arow_b[mi] + ksel);
                    ldmx4(al[mi], st + T_ALO + arow_b[mi] + ksel);
                }
                {
                    uint32_t r[4];
                    ldmx4(r, st + T_WHI + wrow_b + ksel);
                    bh[0][0] = r[0]; bh[1][0] = r[1]; bh[0][1] = r[2]; bh[1][1] = r[3];
                    ldmx4(r, st + T_WLO + wrow_b + ksel);
                    bl[0][0] = r[0]; bl[1][0] = r[1]; bl[0][1] = r[2]; bl[1][1] = r[3];
                }
#pragma unroll
                for (int mi = 0; mi < 2; mi++)
#pragma unroll
                    for (int ni = 0; ni < 2; ni++) {
                        mma16816(acc[mi][ni], ah[mi], bl[ni]);   // qhi @ w1lo
                        mma16816(acc[mi][ni], al[mi], bh[ni]);   // qlo @ w1hi
                    }
            }
            __syncthreads();
            if (cc + 2 < FCHUNKS) issue(cc + 2);
            else                  cp_commit();
            cp_wait<1>();
            __syncthreads();
        }
        cp_wait<0>();

        // epilogue: atomic accumulate into X1
#pragma unroll
        for (int mi = 0; mi < 2; mi++) {
            int r0i = mi * 16 + lr4;
            int r1i = r0i + 8;
            bool v0 = (row0 + r0i) < nrows;
            bool v1 = (row0 + r1i) < nrows;
            size_t g0 = (size_t)srow[r0i] * HH_ + col0;
            size_t g1 = (size_t)srow[r1i] * HH_ + col0;
#pragma unroll
            for (int ni = 0; ni < 2; ni++) {
                int cc = wn + ni * 8 + lc2;
                if (v0) {
                    atomicAdd(C + g0 + cc,     acc[mi][ni][0]);
                    atomicAdd(C + g0 + cc + 1, acc[mi][ni][1]);
                }
                if (v1) {
                    atomicAdd(C + g1 + cc,     acc[mi][ni][2]);
                    atomicAdd(C + g1 + cc + 1, acc[mi][ni][3]);
                }
            }
        }
    }
}

// --------- logits + argmax; scatter confident rows, flag marginal + qlo ---
__global__ void logits_argmax_kernel(const float* __restrict__ W3,
                                     const float* __restrict__ b3,
                                     const float* __restrict__ q)
{
    __shared__ float sW[M_ * HH_];
    __shared__ float sb[M_];
    for (int i = threadIdx.x; i < M_ * HH_; i += blockDim.x) sW[i] = W3[i];
    if (threadIdx.x < M_) sb[threadIdx.x] = b3[threadIdx.x];
    __syncthreads();

    int gw   = (blockIdx.x * blockDim.x + threadIdx.x) >> 5;
    int lane = threadIdx.x & 31;
    int nw   = (gridDim.x * blockDim.x) >> 5;

    for (int row = gw; row < B_; row += nw) {
        const float* x = g_X1 + (size_t)row * HH_;
        float xv[16];
#pragma unroll
        for (int tt = 0; tt < 16; tt++) xv[tt] = fmaxf(x[lane + 32 * tt], 0.0f);
        float best = -3.0e38f, second = -3.0e38f;
        int   bi   = 0;
#pragma unroll
        for (int m = 0; m < M_; m++) {
            float p = 0.0f;
            const float* wrow = sW + m * HH_;
#pragma unroll
            for (int tt = 0; tt < 16; tt++)
                p = fmaf(xv[tt], wrow[lane + 32 * tt], p);
#pragma unroll
            for (int o = 16; o; o >>= 1) p += __shfl_xor_sync(0xffffffffu, p, o);
            p += sb[m];
            if (p > best) { second = best; best = p; bi = m; }
            else if (p > second) second = p;
        }
        if (best - second >= MARGIN_THRESH) {
            if (lane == 0) {
                int p = atomicAdd(&g_cnt[bi], 1);
                g_rows[bi * B_ + p] = row;
            }
        } else {
            if (lane == 0) {
                int fp = atomicAdd(&g_nflag, 1);
                g_flag[fp] = row;
            }
            const float* src = q + (size_t)row * H_;
            const bf16*  hi  = g_qhi + (size_t)row * H_;
            bf16*        lo  = g_qlo + (size_t)row * H_;
            for (int ii = lane; ii < H_ / 2; ii += 32) {
                float a = src[2 * ii], b = src[2 * ii + 1];
                __nv_bfloat162 h = *(const __nv_bfloat162*)(hi + 2 * ii);
                __nv_bfloat162 l(__float2bfloat16_rn(a - __bfloat162float(h.x)),
                                 __float2bfloat16_rn(b - __bfloat162float(h.y)));
                *(__nv_bfloat162*)(lo + 2 * ii) = l;
            }
        }
    }
}

// --------- exact argmax for flagged rows (X1 now exact pre-relu) ---------
__global__ void logits_fix_kernel(const float* __restrict__ W3,
                                  const float* __restrict__ b3)
{
    __shared__ float sW[M_ * HH_];
    __shared__ float sb[M_];
    for (int i = threadIdx.x; i < M_ * HH_; i += blockDim.x) sW[i] = W3[i];
    if (threadIdx.x < M_) sb[threadIdx.x] = b3[threadIdx.x];
    __syncthreads();

    int gw   = (blockIdx.x * blockDim.x + threadIdx.x) >> 5;
    int lane = threadIdx.x & 31;
    int nw   = (gridDim.x * blockDim.x) >> 5;
    int nf   = g_nflag;

    for (int idx = gw; idx < nf; idx += nw) {
        int row = g_flag[idx];
        const float* x = g_X1 + (size_t)row * HH_;
        float xv[16];
#pragma unroll
        for (int tt = 0; tt < 16; tt++) xv[tt] = fmaxf(x[lane + 32 * tt], 0.0f);
        float best = -3.0e38f;
        int   bi   = 0;
#pragma unroll
        for (int m = 0; m < M_; m++) {
            float p = 0.0f;
            const float* wrow = sW + m * HH_;
#pragma unroll
            for (int tt = 0; tt < 16; tt++)
                p = fmaf(xv[tt], wrow[lane + 32 * tt], p);
#pragma unroll
            for (int o = 16; o; o >>= 1) p += __shfl_xor_sync(0xffffffffu, p, o);
            p += sb[m];
            if (p > best) { best = p; bi = m; }
        }
        if (lane == 0) {
            int p = atomicAdd(&g_cnt[bi], 1);
            g_rows[bi * B_ + p] = row;
        }
    }
}

// out = O/max(||O||,eps) + Q  — one WARP per row, shuffle-only reduction
__global__ void finalize_kernel(const float* __restrict__ Q, float* __restrict__ out)
{
    int wid  = threadIdx.x >> 5;
    int lane = threadIdx.x & 31;
    int row  = blockIdx.x * 8 + wid;

    const bf16* o = g_Ob16 + (size_t)row * H_ + lane * 8;
    float ov[4][8];
#pragma unroll
    for (int seg = 0; seg < 4; seg++) {
        uint4 pk = *(const uint4*)(o + seg * 256);
        const __nv_bfloat162* pp = (const __nv_bfloat162*)&pk;
#pragma unroll
        for (int j = 0; j < 4; j++) {
            ov[seg][2*j]   = __bfloat162float(pp[j].x);
            ov[seg][2*j+1] = __bfloat162float(pp[j].y);
        }
    }

    float s = 0.0f;
#pragma unroll
    for (int seg = 0; seg < 4; seg++)
#pragma unroll
        for (int j = 0; j < 8; j++) s += ov[seg][j] * ov[seg][j];
#pragma unroll
    for (int off = 16; off; off >>= 1) s += __shfl_xor_sync(0xffffffffu, s, off);
    float inv = 1.0f / fmaxf(sqrtf(s), 1e-6f);

    const float* qr = Q + (size_t)row * H_ + lane * 8;
    float* orow = out + (size_t)row * H_ + lane * 8;
#pragma unroll
    for (int seg = 0; seg < 4; seg++) {
        float4 qa = *(const float4*)(qr + seg * 256);
        float4 qb = *(const float4*)(qr + seg * 256 + 4);
        float4 ra, rb;
        ra.x = fmaf(ov[seg][0], inv, qa.x); ra.y = fmaf(ov[seg][1], inv, qa.y);
        ra.z = fmaf(ov[seg][2], inv, qa.z); ra.w = fmaf(ov[seg][3], inv, qa.w);
        rb.x = fmaf(ov[seg][4], inv, qb.x); rb.y = fmaf(ov[seg][5], inv, qb.y);
        rb.z = fmaf(ov[seg][6], inv, qb.z); rb.w = fmaf(ov[seg][7], inv, qb.w);
        *(float4*)(orow + seg * 256)     = ra;
        *(float4*)(orow + seg * 256 + 4) = rb;
    }
}

// ---------------- launch ----------------
extern "C" void kernel_launch(void* const* d_in, const int* in_sizes, int n_in,
                              void* d_out, int out_size)
{
    const float* q   = (const float*)d_in[0];
    const float* c1w = (const float*)d_in[1];
    const float* c1b = (const float*)d_in[2];
    const float* c3w = (const float*)d_in[3];
    const float* c3b = (const float*)d_in[4];
    const float* ew1 = (const float*)d_in[5];
    const float* eb1 = (const float*)d_in[6];
    const float* ew2 = (const float*)d_in[7];
    const float* eb2 = (const float*)d_in[8];
    float* out = (float*)d_out;

    void *pqh, *pql, *pw1h, *pw1l, *pe1, *pe2, *pX1, *pHb, *pO;
    cudaGetSymbolAddress(&pqh,  g_qhi);
    cudaGetSymbolAddress(&pql,  g_qlo);
    cudaGetSymbolAddress(&pw1h, g_w1hi);
    cudaGetSymbolAddress(&pw1l, g_w1lo);
    cudaGetSymbolAddress(&pe1,  g_ew1b);
    cudaGetSymbolAddress(&pe2,  g_ew2b);
    cudaGetSymbolAddress(&pX1,  g_X1);
    cudaGetSymbolAddress(&pHb,  g_Hb);
    cudaGetSymbolAddress(&pO,   g_Ob16);

    constexpr int SMEM_FAST = 1024 + 3 * 2 * BM * 128;                     // 99328
    constexpr int SMEM_FLAG = 1024 + 3 * (2 * FBM * 128 + 2 * 128 * 128);  // 123904

    cudaFuncSetAttribute(gemm_mma<0, 0, float>,
                         cudaFuncAttributeMaxDynamicSharedMemorySize, SMEM_FAST);
    cudaFuncSetAttribute(gemm_flag_k,
                         cudaFuncAttributeMaxDynamicSharedMemorySize, SMEM_FLAG);
    cudaFuncSetAttribute(gemm_mma<1, 1, bf16>,
                         cudaFuncAttributeMaxDynamicSharedMemorySize, SMEM_FAST);
    cudaFuncSetAttribute(gemm_mma<1, 0, bf16>,
                         cudaFuncAttributeMaxDynamicSharedMemorySize, SMEM_FAST);

    // 1) all input conversions + counter zeroing (32 elems / thread)
    {
        long total = (long)B_ * H_ + (long)HH_ * H_ + (long)M_ * HH_ * H_ + (long)M_ * H_ * HH_;
        int grid = (int)((total / 32 + 255) / 256);
        bigcvt_k<<<grid, 256>>>(q, c1w, ew1, ew2);
    }
    // 2) gating hidden (single-pass bf16, PRE-relu): X1 = Q@c1w^T + b
    gemm_mma<0, 0, float><<<dim3(B_ / BM, HH_ / BN, 1), NTH, SMEM_FAST>>>(
        (const bf16*)pqh, (const bf16*)pw1h, c1b, (float*)pX1, HH_, H_, B_);
    // 3) logits + argmax: scatter confident, flag marginal (+ build qlo)
    logits_argmax_kernel<<<256, 256>>>(c3w, c3b, q);
    // 4) correction: X1[flagged] += qhi@w1lo + qlo@w1hi  (split-K x8, 256 CTAs)
    gemm_flag_k<<<dim3(8, HH_ / 128, KSPLIT), 256, SMEM_FLAG>>>(
        (const bf16*)pqh, (const bf16*)pql, (const bf16*)pw1h, (const bf16*)pw1l,
        (float*)pX1);
    // 5) exact argmax + scatter for flagged rows
    logits_fix_kernel<<<32, 256>>>(c3w, c3b);
    // 6) expert hidden: H = relu(Qg @ ew1[m]^T + b1[m])  (full grid, bf16 out)
    gemm_mma<1, 1, bf16><<<dim3(B_ / BM, HH_ / BN, M_), NTH, SMEM_FAST>>>(
        (const bf16*)pqh, (const bf16*)pe1, eb1, (bf16*)pHb, HH_, H_, 0);
    // 7) expert out: O = Hg @ ew2[m]^T + b2[m]  (full grid, bf16 out)
    gemm_mma<1, 0, bf16><<<dim3(B_ / BM, H_ / BN, M_), NTH, SMEM_FAST>>>(
        (const bf16*)pHb, (const bf16*)pe2, eb2, (bf16*)pO, H_, HH_, 0);
    // 8) out = normalize(O) + Q
    finalize_kernel<<<B_ / 8, 256>>>(q, out);
}